// round 1
// baseline (speedup 1.0000x reference)
#include <cuda_runtime.h>
#include <math.h>

#define KC 16
#define DD 64

// Precomputed per-component data: W = L^{-1} (lower-tri inverse of Cholesky),
// t = W*mu, c = log(pi) - 0.5*D*log(2pi) - sum(log(diag(L)))
__device__ float g_W[KC][DD][DD];
__device__ float g_t[KC][DD];
__device__ float g_c[KC];

// ---------------- packed f32x2 helpers ----------------
__device__ __forceinline__ unsigned long long fma2(unsigned long long a,
                                                   unsigned long long b,
                                                   unsigned long long c) {
    unsigned long long d;
    asm("fma.rn.f32x2 %0, %1, %2, %3;" : "=l"(d) : "l"(a), "l"(b), "l"(c));
    return d;
}
__device__ __forceinline__ unsigned long long pk2(float lo, float hi) {
    unsigned long long r;
    asm("mov.b64 %0, {%1, %2};" : "=l"(r) : "f"(lo), "f"(hi));
    return r;
}
__device__ __forceinline__ float2 unpk2(unsigned long long v) {
    unsigned int lo, hi;
    asm("mov.b64 {%0, %1}, %2;" : "=r"(lo), "=r"(hi) : "l"(v));
    float2 f;
    f.x = __uint_as_float(lo);
    f.y = __uint_as_float(hi);
    return f;
}

// ---------------- precompute: Cholesky + triangular inverse ----------------
// 16 blocks (one per component) x 64 threads.
__global__ void gmm_precompute_kernel(const float* __restrict__ pi,
                                      const float* __restrict__ mus,
                                      const float* __restrict__ covs) {
    __shared__ float A[DD][DD + 1];
    __shared__ float Wm[DD][DD + 1];
    const int k = blockIdx.x;
    const int tid = threadIdx.x;  // 0..63

    // load cov row tid
    for (int j = 0; j < DD; j++)
        A[tid][j] = covs[((size_t)k * DD + tid) * DD + j];
    __syncthreads();

    // In-place Cholesky (lower), column by column
    for (int j = 0; j < DD; j++) {
        if (tid == j) {
            float s = A[j][j];
            for (int p = 0; p < j; p++) s -= A[j][p] * A[j][p];
            A[j][j] = sqrtf(s);
        }
        __syncthreads();
        if (tid > j) {
            float s = A[tid][j];
            for (int p = 0; p < j; p++) s -= A[tid][p] * A[j][p];
            A[tid][j] = s / A[j][j];
        }
        __syncthreads();
    }

    // Triangular inverse: thread c computes column c of W = L^{-1}
    {
        const int c = tid;
        for (int i = 0; i < DD; i++) {
            if (i < c) {
                Wm[i][c] = 0.0f;
            } else {
                float s = (i == c) ? 1.0f : 0.0f;
                for (int j = c; j < i; j++) s -= A[i][j] * Wm[j][c];
                Wm[i][c] = s / A[i][i];
            }
        }
    }
    __syncthreads();

    // t_i = sum_j W[i][j] * mu[j]; write W row-major
    {
        float ti = 0.0f;
        for (int j = 0; j <= tid; j++)
            ti = fmaf(Wm[tid][j], mus[k * DD + j], ti);
        g_t[k][tid] = ti;
        for (int j = 0; j < DD; j++)
            g_W[k][tid][j] = Wm[tid][j];
    }
    if (tid == 0) {
        float hld = 0.0f;
        for (int i = 0; i < DD; i++) hld += logf(A[i][i]);
        // 0.5 * 64 * log(2*pi) = 32 * 1.8378770664093453
        g_c[k] = logf(pi[k]) - 32.0f * 1.8378770664093453f - hld;
    }
}

// ---------------- main kernel: whitening matvec + softmax ----------------
// 256 threads/block, one point per thread, j-dimension packed f32x2.
__global__ __launch_bounds__(256, 2)
void gmm_main_kernel(const float* __restrict__ X, float* __restrict__ out,
                     int n) {
    __shared__ __align__(16) float Ws[DD * DD];   // 16 KB: current component W
    __shared__ float ts[DD];                      // current component t
    __shared__ float wbuf[KC * 256];              // per-thread weighted logits

    const int tid = threadIdx.x;
    const int point = blockIdx.x * 256 + tid;
    const int ld_pt = (point < n) ? point : (n - 1);

    // Load x into 32 packed f32x2 registers
    unsigned long long px[DD / 2];
    {
        const float4* xr = (const float4*)(X + (size_t)ld_pt * DD);
#pragma unroll
        for (int i = 0; i < DD / 4; i++) {
            float4 v = xr[i];
            px[2 * i]     = pk2(v.x, v.y);
            px[2 * i + 1] = pk2(v.z, v.w);
        }
    }

    for (int k = 0; k < KC; k++) {
        __syncthreads();  // protect Ws/ts from previous iteration's readers
        // cooperative load of W_k (1024 float4) and t_k
        {
            const float4* src = (const float4*)&g_W[k][0][0];
            float4* dst = (float4*)Ws;
#pragma unroll
            for (int i = 0; i < 4; i++)
                dst[tid + 256 * i] = src[tid + 256 * i];
            if (tid < DD) ts[tid] = g_t[k][tid];
        }
        __syncthreads();

        float maha = 0.0f;
#pragma unroll 4
        for (int i = 0; i < DD; i++) {
            unsigned long long acc = 0ull;  // packed {0,0}
            const ulonglong2* wr = (const ulonglong2*)(Ws + i * DD);
#pragma unroll
            for (int j = 0; j < DD / 4; j++) {
                ulonglong2 w2 = wr[j];
                acc = fma2(w2.x, px[2 * j], acc);
                acc = fma2(w2.y, px[2 * j + 1], acc);
            }
            float2 a = unpk2(acc);
            float z = a.x + a.y;
            float d = z - ts[i];
            maha = fmaf(d, d, maha);
        }
        wbuf[k * 256 + tid] = g_c[k] - 0.5f * maha;
    }

    if (point < n) {
        float w[KC];
        float m = -INFINITY;
#pragma unroll
        for (int k = 0; k < KC; k++) {
            w[k] = wbuf[k * 256 + tid];
            m = fmaxf(m, w[k]);
        }
        float e[KC];
        float s = 0.0f;
#pragma unroll
        for (int k = 0; k < KC; k++) {
            e[k] = expf(w[k] - m);
            s += e[k];
        }
        const float inv = 1.0f / s;
        float4* orow = (float4*)(out + (size_t)point * KC);
#pragma unroll
        for (int q = 0; q < KC / 4; q++) {
            orow[q] = make_float4(e[4 * q] * inv, e[4 * q + 1] * inv,
                                  e[4 * q + 2] * inv, e[4 * q + 3] * inv);
        }
    }
}

extern "C" void kernel_launch(void* const* d_in, const int* in_sizes, int n_in,
                              void* d_out, int out_size) {
    const float* X    = (const float*)d_in[0];  // [N, 64]
    const float* pi   = (const float*)d_in[1];  // [16]
    const float* mus  = (const float*)d_in[2];  // [16, 64]
    const float* covs = (const float*)d_in[3];  // [16, 64, 64]
    float* out = (float*)d_out;                 // [N, 16]

    const int n = in_sizes[0] / DD;

    gmm_precompute_kernel<<<KC, DD>>>(pi, mus, covs);
    gmm_main_kernel<<<(n + 255) / 256, 256>>>(X, out, n);
}

// round 2
// speedup vs baseline: 1.0070x; 1.0070x over previous
#include <cuda_runtime.h>
#include <math.h>

#define KC 16
#define DD 64

// Precomputed per-component data: W = L^{-1} (lower-tri inverse of Cholesky),
// t = W*mu, c = log(pi) - 0.5*D*log(2pi) - sum(log(diag(L)))
__device__ float g_W[KC][DD][DD];
__device__ float g_t[KC][DD];
__device__ float g_c[KC];

// ---------------- packed f32x2 helpers ----------------
__device__ __forceinline__ unsigned long long fma2(unsigned long long a,
                                                   unsigned long long b,
                                                   unsigned long long c) {
    unsigned long long d;
    asm("fma.rn.f32x2 %0, %1, %2, %3;" : "=l"(d) : "l"(a), "l"(b), "l"(c));
    return d;
}
__device__ __forceinline__ unsigned long long add2(unsigned long long a,
                                                   unsigned long long b) {
    unsigned long long d;
    asm("add.rn.f32x2 %0, %1, %2;" : "=l"(d) : "l"(a), "l"(b));
    return d;
}
__device__ __forceinline__ unsigned long long pk2(float lo, float hi) {
    unsigned long long r;
    asm("mov.b64 %0, {%1, %2};" : "=l"(r) : "f"(lo), "f"(hi));
    return r;
}
__device__ __forceinline__ float2 unpk2(unsigned long long v) {
    unsigned int lo, hi;
    asm("mov.b64 {%0, %1}, %2;" : "=r"(lo), "=r"(hi) : "l"(v));
    float2 f;
    f.x = __uint_as_float(lo);
    f.y = __uint_as_float(hi);
    return f;
}

// ---------------- cp.async helpers ----------------
__device__ __forceinline__ unsigned smem_u32(const void* p) {
    return (unsigned)__cvta_generic_to_shared(p);
}
__device__ __forceinline__ void cp16(unsigned dst, const void* src) {
    asm volatile("cp.async.cg.shared.global [%0], [%1], 16;\n"
                 :: "r"(dst), "l"(src));
}
__device__ __forceinline__ void cp_commit() {
    asm volatile("cp.async.commit_group;\n");
}
template <int N> __device__ __forceinline__ void cp_wait() {
    asm volatile("cp.async.wait_group %0;\n" :: "n"(N));
}

// ---------------- precompute: Cholesky + triangular inverse ----------------
// 16 blocks (one per component) x 64 threads.  (unchanged from R1 — proven)
__global__ void gmm_precompute_kernel(const float* __restrict__ pi,
                                      const float* __restrict__ mus,
                                      const float* __restrict__ covs) {
    __shared__ float A[DD][DD + 1];
    __shared__ float Wm[DD][DD + 1];
    const int k = blockIdx.x;
    const int tid = threadIdx.x;  // 0..63

    for (int j = 0; j < DD; j++)
        A[tid][j] = covs[((size_t)k * DD + tid) * DD + j];
    __syncthreads();

    for (int j = 0; j < DD; j++) {
        if (tid == j) {
            float s0 = A[j][j], s1 = 0.0f;
            for (int p = 0; p + 1 < j; p += 2) {
                s0 -= A[j][p] * A[j][p];
                s1 -= A[j][p + 1] * A[j][p + 1];
            }
            if (j & 1) s0 -= A[j][j - 1] * A[j][j - 1];
            A[j][j] = sqrtf(s0 + s1);
        }
        __syncthreads();
        if (tid > j) {
            float s0 = A[tid][j], s1 = 0.0f;
            for (int p = 0; p + 1 < j; p += 2) {
                s0 -= A[tid][p] * A[j][p];
                s1 -= A[tid][p + 1] * A[j][p + 1];
            }
            if (j & 1) s0 -= A[tid][j - 1] * A[j][j - 1];
            A[tid][j] = (s0 + s1) / A[j][j];
        }
        __syncthreads();
    }

    // Triangular inverse: thread c computes column c of W = L^{-1}
    {
        const int c = tid;
        for (int i = 0; i < DD; i++) {
            if (i < c) {
                Wm[i][c] = 0.0f;
            } else {
                float s = (i == c) ? 1.0f : 0.0f;
                for (int j = c; j < i; j++) s -= A[i][j] * Wm[j][c];
                Wm[i][c] = s / A[i][i];
            }
        }
    }
    __syncthreads();

    {
        float ti = 0.0f;
        for (int j = 0; j <= tid; j++)
            ti = fmaf(Wm[tid][j], mus[k * DD + j], ti);
        g_t[k][tid] = ti;
        for (int j = 0; j < DD; j++)
            g_W[k][tid][j] = Wm[tid][j];
    }
    if (tid == 0) {
        float hld = 0.0f;
        for (int i = 0; i < DD; i++) hld += logf(A[i][i]);
        g_c[k] = logf(pi[k]) - 32.0f * 1.8378770664093453f - hld;
    }
}

// ---------------- main kernel ----------------
// 256 threads/block, one point per thread, j-dimension packed f32x2.
// Double-buffered W in SMEM via cp.async; logits in registers.
__global__ __launch_bounds__(256, 2)
void gmm_main_kernel(const float* __restrict__ X, float* __restrict__ out,
                     int n) {
    __shared__ __align__(16) float Ws[2][DD * DD];  // 2 x 16 KB
    __shared__ __align__(16) float ts[2][DD];
    __shared__ float cs[KC];

    const int tid = threadIdx.x;
    const int point = blockIdx.x * 256 + tid;
    const int ld_pt = (point < n) ? point : (n - 1);

    if (tid < KC) cs[tid] = g_c[tid];

    // Load x into 32 packed f32x2 registers
    unsigned long long px[DD / 2];
    {
        const float4* xr = (const float4*)(X + (size_t)ld_pt * DD);
#pragma unroll
        for (int i = 0; i < DD / 4; i++) {
            float4 v = xr[i];
            px[2 * i]     = pk2(v.x, v.y);
            px[2 * i + 1] = pk2(v.z, v.w);
        }
    }

    // prefetch component 0 into buffer 0
    {
        const float4* src = (const float4*)&g_W[0][0][0];
        unsigned dst = smem_u32(&Ws[0][0]);
#pragma unroll
        for (int i = 0; i < 4; i++)
            cp16(dst + (unsigned)(tid + 256 * i) * 16, src + tid + 256 * i);
        if (tid < DD / 4)
            cp16(smem_u32(&ts[0][0]) + (unsigned)tid * 16,
                 ((const float4*)&g_t[0][0]) + tid);
        cp_commit();
    }

    float logit[KC];

#pragma unroll 1
    for (int k = 0; k < KC; k++) {
        const int cur = k & 1;
        if (k < KC - 1) {
            const int nxt = (k + 1) & 1;
            const float4* src = (const float4*)&g_W[k + 1][0][0];
            unsigned dst = smem_u32(&Ws[nxt][0]);
#pragma unroll
            for (int i = 0; i < 4; i++)
                cp16(dst + (unsigned)(tid + 256 * i) * 16, src + tid + 256 * i);
            if (tid < DD / 4)
                cp16(smem_u32(&ts[nxt][0]) + (unsigned)tid * 16,
                     ((const float4*)&g_t[k + 1][0]) + tid);
            cp_commit();
            cp_wait<1>();   // current tile (k) complete for this thread
        } else {
            cp_wait<0>();
        }
        __syncthreads();    // all threads' copies of tile k visible

        const float* Wc = Ws[cur];
        const float* tc = ts[cur];

        float maha = 0.0f;
#pragma unroll 4
        for (int i = 0; i < DD; i++) {
            unsigned long long a0 = 0ull, a1 = 0ull;  // two chains
            const ulonglong2* wr = (const ulonglong2*)(Wc + i * DD);
#pragma unroll
            for (int j = 0; j < DD / 4; j++) {
                ulonglong2 w2 = wr[j];
                a0 = fma2(w2.x, px[2 * j], a0);
                a1 = fma2(w2.y, px[2 * j + 1], a1);
            }
            float2 a = unpk2(add2(a0, a1));
            float d = (a.x + a.y) - tc[i];
            maha = fmaf(d, d, maha);
        }
        logit[k] = cs[k] - 0.5f * maha;

        __syncthreads();  // compute on buf[cur] done before it is re-filled
    }

    if (point < n) {
        float m = -INFINITY;
#pragma unroll
        for (int k = 0; k < KC; k++) m = fmaxf(m, logit[k]);
        float e[KC];
        float s = 0.0f;
#pragma unroll
        for (int k = 0; k < KC; k++) {
            e[k] = __expf(logit[k] - m);
            s += e[k];
        }
        const float inv = 1.0f / s;
        float4* orow = (float4*)(out + (size_t)point * KC);
#pragma unroll
        for (int q = 0; q < KC / 4; q++) {
            orow[q] = make_float4(e[4 * q] * inv, e[4 * q + 1] * inv,
                                  e[4 * q + 2] * inv, e[4 * q + 3] * inv);
        }
    }
}

extern "C" void kernel_launch(void* const* d_in, const int* in_sizes, int n_in,
                              void* d_out, int out_size) {
    const float* X    = (const float*)d_in[0];  // [N, 64]
    const float* pi   = (const float*)d_in[1];  // [16]
    const float* mus  = (const float*)d_in[2];  // [16, 64]
    const float* covs = (const float*)d_in[3];  // [16, 64, 64]
    float* out = (float*)d_out;                 // [N, 16]

    const int n = in_sizes[0] / DD;

    gmm_precompute_kernel<<<KC, DD>>>(pi, mus, covs);
    gmm_main_kernel<<<(n + 255) / 256, 256>>>(X, out, n);
}

// round 3
// speedup vs baseline: 1.9219x; 1.9085x over previous
#include <cuda_runtime.h>
#include <math.h>

#define KC 16
#define DD 64
#define NMAX 204800

// Precomputed per-component data: W = L^{-1} (lower-tri), t = W*mu,
// c = log(pi) - 0.5*D*log(2pi) - sum(log(diag(L)))
__device__ float g_W[KC][DD][DD];
__device__ float g_t[KC][DD];
__device__ float g_c[KC];
__device__ float g_logits[KC][NMAX];   // [K][N] scratch, coalesced writes

// ---------------- packed f32x2 helpers ----------------
__device__ __forceinline__ unsigned long long fma2(unsigned long long a,
                                                   unsigned long long b,
                                                   unsigned long long c) {
    unsigned long long d;
    asm("fma.rn.f32x2 %0, %1, %2, %3;" : "=l"(d) : "l"(a), "l"(b), "l"(c));
    return d;
}
__device__ __forceinline__ unsigned long long add2(unsigned long long a,
                                                   unsigned long long b) {
    unsigned long long d;
    asm("add.rn.f32x2 %0, %1, %2;" : "=l"(d) : "l"(a), "l"(b));
    return d;
}
__device__ __forceinline__ unsigned long long pk2(float lo, float hi) {
    unsigned long long r;
    asm("mov.b64 %0, {%1, %2};" : "=l"(r) : "f"(lo), "f"(hi));
    return r;
}
__device__ __forceinline__ float2 unpk2(unsigned long long v) {
    unsigned int lo, hi;
    asm("mov.b64 {%0, %1}, %2;" : "=r"(lo), "=r"(hi) : "l"(v));
    float2 f;
    f.x = __uint_as_float(lo);
    f.y = __uint_as_float(hi);
    return f;
}

// ---------------- cp.async helpers ----------------
__device__ __forceinline__ unsigned smem_u32(const void* p) {
    return (unsigned)__cvta_generic_to_shared(p);
}
__device__ __forceinline__ void cp16(unsigned dst, const void* src) {
    asm volatile("cp.async.cg.shared.global [%0], [%1], 16;\n"
                 :: "r"(dst), "l"(src));
}
__device__ __forceinline__ void cp_commit() {
    asm volatile("cp.async.commit_group;\n");
}
template <int N> __device__ __forceinline__ void cp_wait() {
    asm volatile("cp.async.wait_group %0;\n" :: "n"(N));
}

// ---------------- precompute: Cholesky + triangular inverse ----------------
__global__ void gmm_precompute_kernel(const float* __restrict__ pi,
                                      const float* __restrict__ mus,
                                      const float* __restrict__ covs) {
    __shared__ float A[DD][DD + 1];
    __shared__ float Wm[DD][DD + 1];
    const int k = blockIdx.x;
    const int tid = threadIdx.x;  // 0..63

    for (int j = 0; j < DD; j++)
        A[tid][j] = covs[((size_t)k * DD + tid) * DD + j];
    __syncthreads();

    for (int j = 0; j < DD; j++) {
        if (tid == j) {
            float s = A[j][j];
            for (int p = 0; p < j; p++) s -= A[j][p] * A[j][p];
            A[j][j] = sqrtf(s);
        }
        __syncthreads();
        if (tid > j) {
            float s = A[tid][j];
            for (int p = 0; p < j; p++) s -= A[tid][p] * A[j][p];
            A[tid][j] = s / A[j][j];
        }
        __syncthreads();
    }

    // thread c computes column c of W = L^{-1}
    {
        const int c = tid;
        for (int i = 0; i < DD; i++) {
            if (i < c) {
                Wm[i][c] = 0.0f;
            } else {
                float s = (i == c) ? 1.0f : 0.0f;
                for (int j = c; j < i; j++) s -= A[i][j] * Wm[j][c];
                Wm[i][c] = s / A[i][i];
            }
        }
    }
    __syncthreads();

    {
        float ti = 0.0f;
        for (int j = 0; j <= tid; j++)
            ti = fmaf(Wm[tid][j], mus[k * DD + j], ti);
        g_t[k][tid] = ti;
        for (int j = 0; j < DD; j++)
            g_W[k][tid][j] = Wm[tid][j];
    }
    if (tid == 0) {
        float hld = 0.0f;
        for (int i = 0; i < DD; i++) hld += logf(A[i][i]);
        g_c[k] = logf(pi[k]) - 32.0f * 1.8378770664093453f - hld;
    }
}

// ---------------- main kernel ----------------
// 128 threads/block, TWO points per thread, triangular matvec.
__global__ __launch_bounds__(128, 3)
void gmm_main_kernel(const float* __restrict__ X, int n) {
    __shared__ __align__(16) float Ws[2][DD * DD];  // 2 x 16 KB
    __shared__ __align__(16) float ts[2][DD];
    __shared__ float cs[KC];

    const int tid = threadIdx.x;
    const int p0 = (blockIdx.x * 128 + tid) * 2;
    const int ld0 = (p0 < n) ? p0 : (n - 1);
    const int ld1 = (p0 + 1 < n) ? (p0 + 1) : (n - 1);

    if (tid < KC) cs[tid] = g_c[tid];

    // Load both points into packed f32x2 registers (j-packing)
    unsigned long long pxA[DD / 2], pxB[DD / 2];
    {
        const float4* xr0 = (const float4*)(X + (size_t)ld0 * DD);
        const float4* xr1 = (const float4*)(X + (size_t)ld1 * DD);
#pragma unroll
        for (int i = 0; i < DD / 4; i++) {
            float4 v = xr0[i];
            pxA[2 * i]     = pk2(v.x, v.y);
            pxA[2 * i + 1] = pk2(v.z, v.w);
            float4 u = xr1[i];
            pxB[2 * i]     = pk2(u.x, u.y);
            pxB[2 * i + 1] = pk2(u.z, u.w);
        }
    }

    // prefetch component 0 into buffer 0
    {
        const float4* src = (const float4*)&g_W[0][0][0];
        unsigned dst = smem_u32(&Ws[0][0]);
#pragma unroll
        for (int i = 0; i < 8; i++)
            cp16(dst + (unsigned)(tid + 128 * i) * 16, src + tid + 128 * i);
        if (tid < DD / 4)
            cp16(smem_u32(&ts[0][0]) + (unsigned)tid * 16,
                 ((const float4*)&g_t[0][0]) + tid);
        cp_commit();
    }

#pragma unroll 1
    for (int k = 0; k < KC; k++) {
        const int cur = k & 1;
        if (k < KC - 1) {
            const int nxt = (k + 1) & 1;
            const float4* src = (const float4*)&g_W[k + 1][0][0];
            unsigned dst = smem_u32(&Ws[nxt][0]);
#pragma unroll
            for (int i = 0; i < 8; i++)
                cp16(dst + (unsigned)(tid + 128 * i) * 16, src + tid + 128 * i);
            if (tid < DD / 4)
                cp16(smem_u32(&ts[nxt][0]) + (unsigned)tid * 16,
                     ((const float4*)&g_t[k + 1][0]) + tid);
            cp_commit();
            cp_wait<1>();
        } else {
            cp_wait<0>();
        }
        __syncthreads();

        const float* Wc = Ws[cur];
        const float* tc = ts[cur];

        float mahaA = 0.0f, mahaB = 0.0f;
        // rows grouped by 4; group g needs cols [0, 4g+4) — triangular W
#pragma unroll
        for (int g = 0; g < DD / 4; g++) {
#pragma unroll
            for (int r = 0; r < 4; r++) {
                const int i = 4 * g + r;
                unsigned long long a0 = 0ull, a1 = 0ull;
                unsigned long long b0 = 0ull, b1 = 0ull;
                const ulonglong2* wr = (const ulonglong2*)(Wc + i * DD);
#pragma unroll
                for (int j = 0; j <= g; j++) {
                    ulonglong2 w2 = wr[j];
                    a0 = fma2(w2.x, pxA[2 * j], a0);
                    a1 = fma2(w2.y, pxA[2 * j + 1], a1);
                    b0 = fma2(w2.x, pxB[2 * j], b0);
                    b1 = fma2(w2.y, pxB[2 * j + 1], b1);
                }
                const float ti = tc[i];
                float2 a = unpk2(add2(a0, a1));
                float da = (a.x + a.y) - ti;
                mahaA = fmaf(da, da, mahaA);
                float2 b = unpk2(add2(b0, b1));
                float db = (b.x + b.y) - ti;
                mahaB = fmaf(db, db, mahaB);
            }
        }
        if (p0 < n) {
            float2 lw = make_float2(cs[k] - 0.5f * mahaA,
                                    cs[k] - 0.5f * mahaB);
            if (p0 + 1 < n) {
                *(float2*)&g_logits[k][p0] = lw;
            } else {
                g_logits[k][p0] = lw.x;
            }
        }
        __syncthreads();
    }
}

// ---------------- softmax pass ----------------
__global__ __launch_bounds__(256)
void gmm_softmax_kernel(float* __restrict__ out, int n) {
    const int p = blockIdx.x * 256 + threadIdx.x;
    if (p >= n) return;
    float w[KC];
    float m = -INFINITY;
#pragma unroll
    for (int k = 0; k < KC; k++) {
        w[k] = g_logits[k][p];
        m = fmaxf(m, w[k]);
    }
    float s = 0.0f;
#pragma unroll
    for (int k = 0; k < KC; k++) {
        w[k] = __expf(w[k] - m);
        s += w[k];
    }
    const float inv = 1.0f / s;
    float4* orow = (float4*)(out + (size_t)p * KC);
#pragma unroll
    for (int q = 0; q < KC / 4; q++)
        orow[q] = make_float4(w[4 * q] * inv, w[4 * q + 1] * inv,
                              w[4 * q + 2] * inv, w[4 * q + 3] * inv);
}

extern "C" void kernel_launch(void* const* d_in, const int* in_sizes, int n_in,
                              void* d_out, int out_size) {
    const float* X    = (const float*)d_in[0];  // [N, 64]
    const float* pi   = (const float*)d_in[1];  // [16]
    const float* mus  = (const float*)d_in[2];  // [16, 64]
    const float* covs = (const float*)d_in[3];  // [16, 64, 64]
    float* out = (float*)d_out;                 // [N, 16]

    const int n = in_sizes[0] / DD;

    gmm_precompute_kernel<<<KC, DD>>>(pi, mus, covs);
    const int pts_per_block = 256;  // 128 threads x 2 points
    gmm_main_kernel<<<(n + pts_per_block - 1) / pts_per_block, 128>>>(X, n);
    gmm_softmax_kernel<<<(n + 255) / 256, 256>>>(out, n);
}